// round 2
// baseline (speedup 1.0000x reference)
#include <cuda_runtime.h>
#include <math.h>

#define Bb   2
#define Nn   4096
#define GNNc 64
#define LATc 128
#define KG   12
#define KP   8
#define Mm   32768
#define BN   (Bb*Nn)   // 8192
#define BM   (Bb*Mm)   // 65536
#define GPP  16        // grid points per block in k_proj

// ---------------- scratch (static device globals; no allocation) -------------
__device__ float g_x  [BN*GNNc];
__device__ float g_v  [BN*GNNc];
__device__ float g_o  [BN*GNNc];
__device__ float g_pf [BN*LATc];
__device__ int   g_nbr[BN*KG];
__device__ int   g_gidx[BM*KP];
__device__ float g_gd2 [BM*KP];
__device__ float g_chsum[GNNc];
__device__ float g_s[GNNc];

__device__ __forceinline__ float gelu_f(float x){
    return 0.5f * x * (1.0f + erff(x * 0.7071067811865476f));
}

// exact-rounding helpers matching XLA's op-by-op f32 semantics
__device__ __forceinline__ float sqsum_A(float x, float y, float z){
    // elementwise square (rounded) then left-assoc reduce: ((x^2 + y^2) + z^2)
    return __fadd_rn(__fadd_rn(__fmul_rn(x,x), __fmul_rn(y,y)), __fmul_rn(z,z));
}
__device__ __forceinline__ float dot3_gemm(float a0,float a1,float a2,
                                           float b0,float b1,float b2){
    // ascending-k FMA with zero-init acc: fma(a2,b2, fma(a1,b1, round(a0*b0)))
    return __fmaf_rn(a2,b2, __fmaf_rn(a1,b1, __fmul_rn(a0,b0)));
}
__device__ __forceinline__ float d2_ref(float asum, float bsum, float dot){
    // round(asum+bsum) - 2*dot   (2*dot exact)
    return __fadd_rn(__fadd_rn(asum,bsum), __fmul_rn(-2.0f, dot));
}
// grid coordinate matching np.linspace(-1,1,32) (float64 then cast to f32)
__device__ __forceinline__ float grid_coord(int i){
    return (float)(-1.0 + (2.0/31.0) * (double)i);
}

// ---------------- x = feats @ W_in + b_in ------------------------------------
__global__ void k_input(const float* __restrict__ feats,
                        const float* __restrict__ W,
                        const float* __restrict__ bias){
    int t = blockIdx.x*blockDim.x + threadIdx.x;
    if (t >= BN*GNNc) return;
    int row = t >> 6, c = t & 63;
    const float* f = feats + row*9;
    float acc = bias[c];
    #pragma unroll
    for (int j=0;j<9;j++) acc = fmaf(f[j], W[j*GNNc + c], acc);
    g_x[t] = acc;
}

// ---------------- self kNN: top-12 excluding self -----------------------------
__global__ void k_knn_self(const float* __restrict__ coords){
    extern __shared__ float4 sc[];          // Nn float4 = 64 KB
    int q = blockIdx.x*blockDim.x + threadIdx.x;   // 0..BN-1
    int b  = q / Nn;
    int il = q % Nn;
    const float* cb = coords + b*Nn*3;
    for (int j = threadIdx.x; j < Nn; j += blockDim.x){
        float x = cb[j*3], y = cb[j*3+1], z = cb[j*3+2];
        sc[j] = make_float4(x,y,z, sqsum_A(x,y,z));
    }
    __syncthreads();
    float4 qf = sc[il];
    float kd[KG]; int ki[KG];
    #pragma unroll
    for (int r=0;r<KG;r++){ kd[r]=3.4e38f; ki[r]=0; }
    for (int j=0;j<Nn;j++){
        float4 f = sc[j];
        float dot = dot3_gemm(qf.x,qf.y,qf.z, f.x,f.y,f.z);
        float d2  = d2_ref(qf.w, f.w, dot);
        if (j == il) d2 = 3.5e38f;
        if (d2 < kd[KG-1]){
            kd[KG-1] = d2; ki[KG-1] = j;
            #pragma unroll
            for (int r=KG-1; r>0; r--){
                if (kd[r] < kd[r-1]) {
                    float td=kd[r]; kd[r]=kd[r-1]; kd[r-1]=td;
                    int   ti=ki[r]; ki[r]=ki[r-1]; ki[r-1]=ti;
                }
            }
        }
    }
    #pragma unroll
    for (int r=0;r<KG;r++) g_nbr[q*KG + r] = ki[r];
}

// ---------------- grid kNN: top-8 (stores d2 too) -----------------------------
__global__ void k_knn_grid(const float* __restrict__ coords){
    extern __shared__ float4 sc[];
    int q = blockIdx.x*blockDim.x + threadIdx.x;   // 0..BM-1
    int b = q / Mm;
    int m = q % Mm;
    const float* cb = coords + b*Nn*3;
    for (int j = threadIdx.x; j < Nn; j += blockDim.x){
        float x = cb[j*3], y = cb[j*3+1], z = cb[j*3+2];
        sc[j] = make_float4(x,y,z, sqsum_A(x,y,z));
    }
    __syncthreads();
    float px = grid_coord( m        & 31);
    float py = grid_coord((m >> 5)  & 31);
    float pz = grid_coord( m >> 10      );
    float pp = sqsum_A(px,py,pz);
    float kd[KP]; int ki[KP];
    #pragma unroll
    for (int r=0;r<KP;r++){ kd[r]=3.4e38f; ki[r]=0; }
    for (int j=0;j<Nn;j++){
        float4 f = sc[j];
        float dot = dot3_gemm(px,py,pz, f.x,f.y,f.z);
        float d2  = d2_ref(pp, f.w, dot);
        if (d2 < kd[KP-1]){
            kd[KP-1] = d2; ki[KP-1] = j;
            #pragma unroll
            for (int r=KP-1; r>0; r--){
                if (kd[r] < kd[r-1]) {
                    float td=kd[r]; kd[r]=kd[r-1]; kd[r-1]=td;
                    int   ti=ki[r]; ki[r]=ki[r-1]; ki[r-1]=ti;
                }
            }
        }
    }
    #pragma unroll
    for (int r=0;r<KP;r++){
        g_gidx[q*KP + r] = ki[r];
        g_gd2 [q*KP + r] = kd[r];
    }
}

// ---------------- generic row GEMM Y = X@W + b --------------------------------
template<int IN, int OUT>
__global__ void k_rowgemm(const float* __restrict__ X,
                          const float* __restrict__ W,
                          const float* __restrict__ bias,
                          float* __restrict__ Y){
    __shared__ float Ws[IN*OUT];
    __shared__ float xs[IN];
    for (int t=threadIdx.x; t<IN*OUT; t+=blockDim.x) Ws[t]=W[t];
    int c = threadIdx.x;             // blockDim == OUT
    float bc = bias[c];
    for (int r = blockIdx.x; r < BN; r += gridDim.x){
        __syncthreads();
        for (int t=threadIdx.x; t<IN; t+=blockDim.x) xs[t] = X[r*IN + t];
        __syncthreads();
        float acc = bc;
        #pragma unroll
        for (int j=0;j<IN;j++) acc = fmaf(xs[j], Ws[j*OUT+c], acc);
        Y[r*OUT+c] = acc;
    }
}

// ---------------- zero channel sums -------------------------------------------
__global__ void k_zero64(){ g_chsum[threadIdx.x] = 0.0f; }

// ---------------- GNO message passing: out + channel sums ---------------------
__global__ void k_gno_out(const float* __restrict__ coords,
                          const float* __restrict__ kW1, const float* __restrict__ kb1,
                          const float* __restrict__ kW2, const float* __restrict__ kb2){
    __shared__ float W1s[96], b1s[32], W2s[32*64], b2s[64];
    __shared__ float gsh[KG*32];
    __shared__ float relb[KG][3];
    __shared__ int   ji[KG];
    int p = blockIdx.x;              // 0..BN-1
    int b = p / Nn, i = p % Nn;
    int c = threadIdx.x;             // 64 threads
    for (int t=c; t<96; t+=64)   W1s[t]=kW1[t];
    if (c<32)                    b1s[c]=kb1[c];
    for (int t=c; t<2048; t+=64) W2s[t]=kW2[t];
    b2s[c]=kb2[c];
    const float* cb = coords + b*Nn*3;
    if (c < KG){
        float cx=cb[i*3], cy=cb[i*3+1], cz=cb[i*3+2];
        int j = g_nbr[p*KG + c];
        ji[c]=j;
        relb[c][0]=cb[j*3]  -cx;
        relb[c][1]=cb[j*3+1]-cy;
        relb[c][2]=cb[j*3+2]-cz;
    }
    __syncthreads();
    for (int t=c; t<KG*32; t+=64){
        int k=t>>5, h=t&31;
        float d = fmaf(relb[k][2], W1s[64+h],
                  fmaf(relb[k][1], W1s[32+h],
                  fmaf(relb[k][0], W1s[h], b1s[h])));
        gsh[t] = gelu_f(d);
    }
    __syncthreads();
    float outc = 0.0f;
    float b2c  = b2s[c];
    #pragma unroll
    for (int k=0;k<KG;k++){
        float vn = g_v[(b*Nn + ji[k])*GNNc + c];
        float s = b2c;
        #pragma unroll
        for (int h=0;h<32;h++) s = fmaf(gsh[k*32+h], W2s[h*64+c], s);
        outc = fmaf(s, vn, outc);
    }
    g_o[p*GNNc + c] = outc;
    atomicAdd(&g_chsum[c], outc);
}

// ---------------- squeeze-excite gate ------------------------------------------
__global__ void k_se(const float* __restrict__ seW1, const float* __restrict__ seW2){
    __shared__ float ms[64], hs[16];
    int c = threadIdx.x;
    ms[c] = g_chsum[c] * (1.0f/(float)BN);
    __syncthreads();
    if (c < 16){
        float a=0.f;
        #pragma unroll
        for (int j=0;j<64;j++) a = fmaf(ms[j], seW1[j*16+c], a);
        hs[c] = gelu_f(a);
    }
    __syncthreads();
    float a=0.f;
    #pragma unroll
    for (int h=0;h<16;h++) a = fmaf(hs[h], seW2[h*64+c], a);
    g_s[c] = 1.0f/(1.0f + expf(-a));
}

// ---------------- x = LN(gelu(out*s + v)) ---------------------------------------
__global__ void k_gno_ln(const float* __restrict__ lng, const float* __restrict__ lnb){
    __shared__ float r1[64], r2[64];
    int c = threadIdx.x;
    float sc = g_s[c];
    float gc = lng[c], bc = lnb[c];
    for (int r = blockIdx.x; r < BN; r += gridDim.x){
        float y = gelu_f(fmaf(g_o[r*64+c], sc, g_v[r*64+c]));
        r1[c]=y; r2[c]=y*y;
        __syncthreads();
        #pragma unroll
        for (int s=32; s>0; s>>=1){
            if (c < s){ r1[c]+=r1[c+s]; r2[c]+=r2[c+s]; }
            __syncthreads();
        }
        float mean = r1[0]*(1.0f/64.0f);
        float var  = r2[0]*(1.0f/64.0f) - mean*mean;
        g_x[r*64+c] = (y-mean)*rsqrtf(var+1e-5f)*gc + bc;
        __syncthreads();
    }
}

// ---------------- fused projection + LN (dominant kernel) -----------------------
__global__ void __launch_bounds__(128) k_proj(const float* __restrict__ coords,
        const float* __restrict__ W1, const float* __restrict__ b1,
        const float* __restrict__ W2, const float* __restrict__ b2,
        const float* __restrict__ lng, const float* __restrict__ lnb,
        float* __restrict__ out){
    extern __shared__ float sh[];
    float* W2s   = sh;               // 16384
    float* W1s   = sh + 16384;       // 384
    float* b1s   = sh + 16768;       // 128
    float* b2s   = sh + 16896;       // 128
    float* lgs   = sh + 17024;       // 128
    float* lbs   = sh + 17152;       // 128
    float* ht    = sh + 17280;       // 128*8, 16B aligned
    float* outsh = sh + 18304;       // 128*(GPP+1)
    float* relb  = sh + 18304 + 128*(GPP+1);   // 24
    float* wr    = relb + 24;        // 8
    int*   ji    = (int*)(wr + 8);   // 8
    float* red1  = wr + 16;          // 4
    float* red2  = wr + 20;          // 4

    int tid = threadIdx.x;
    for (int t=tid; t<16384; t+=128) W2s[t]=W2[t];
    for (int t=tid; t<384;   t+=128) W1s[t]=W1[t];
    b1s[tid]=b1[tid]; b2s[tid]=b2[tid]; lgs[tid]=lng[tid]; lbs[tid]=lnb[tid];

    int base = blockIdx.x * GPP;
    int b  = base / Mm;
    int m0 = base % Mm;
    const float* cb = coords + b*Nn*3;
    __syncthreads();

    for (int gi=0; gi<GPP; gi++){
        int m = m0 + gi;
        float px = grid_coord( m        & 31);
        float py = grid_coord((m >> 5)  & 31);
        float pz = grid_coord( m >> 10      );
        if (tid < KP){
            long qk = (long)(b*Mm + m)*KP + tid;
            int id  = g_gidx[qk];
            float d2 = g_gd2[qk];
            float dist = sqrtf(fmaxf(d2, 1e-12f));
            wr[tid] = 1.0f/(dist + 1e-6f);
            ji[tid] = id;
            relb[tid*3+0] = px - cb[id*3];
            relb[tid*3+1] = py - cb[id*3+1];
            relb[tid*3+2] = pz - cb[id*3+2];
        }
        __syncthreads();

        // prefetch pf rows for the 8 neighbors (hides latency behind phase 1)
        float pfv[KP];
        #pragma unroll
        for (int k=0;k<KP;k++) pfv[k] = g_pf[(b*Nn + ji[k])*LATc + tid];

        // phase 1: hidden vector h (thread = hidden unit j), stored transposed
        {
            float w0=W1s[tid], w1=W1s[128+tid], w2w=W1s[256+tid], bb=b1s[tid];
            #pragma unroll
            for (int k=0;k<KP;k++){
                float d = fmaf(relb[k*3+2], w2w,
                          fmaf(relb[k*3+1], w1,
                          fmaf(relb[k*3+0], w0, bb)));
                ht[tid*8+k] = gelu_f(d);
            }
        }
        __syncthreads();

        // phase 2: thread = output channel c; 8 accumulators (one per neighbor)
        float a0=0,a1=0,a2=0,a3=0,a4=0,a5=0,a6=0,a7=0;
        const float4* htv = (const float4*)ht;
        #pragma unroll 4
        for (int j=0;j<128;j++){
            float w  = W2s[j*128 + tid];
            float4 hA = htv[j*2];
            float4 hB = htv[j*2+1];
            a0=fmaf(hA.x,w,a0); a1=fmaf(hA.y,w,a1);
            a2=fmaf(hA.z,w,a2); a3=fmaf(hA.w,w,a3);
            a4=fmaf(hB.x,w,a4); a5=fmaf(hB.y,w,a5);
            a6=fmaf(hB.z,w,a6); a7=fmaf(hB.w,w,a7);
        }
        float wsum = 0.f;
        #pragma unroll
        for (int k=0;k<KP;k++) wsum += wr[k];
        float b2c = b2s[tid];
        float o = 0.f;
        o = fmaf((a0+b2c)*wr[0], pfv[0], o);
        o = fmaf((a1+b2c)*wr[1], pfv[1], o);
        o = fmaf((a2+b2c)*wr[2], pfv[2], o);
        o = fmaf((a3+b2c)*wr[3], pfv[3], o);
        o = fmaf((a4+b2c)*wr[4], pfv[4], o);
        o = fmaf((a5+b2c)*wr[5], pfv[5], o);
        o = fmaf((a6+b2c)*wr[6], pfv[6], o);
        o = fmaf((a7+b2c)*wr[7], pfv[7], o);
        o /= wsum;

        // LayerNorm over 128 channels
        float s1 = o, s2 = o*o;
        #pragma unroll
        for (int off=16; off>0; off>>=1){
            s1 += __shfl_xor_sync(0xffffffffu, s1, off);
            s2 += __shfl_xor_sync(0xffffffffu, s2, off);
        }
        int wid = tid>>5;
        if ((tid&31)==0){ red1[wid]=s1; red2[wid]=s2; }
        __syncthreads();
        float t1 = red1[0]+red1[1]+red1[2]+red1[3];
        float t2 = red2[0]+red2[1]+red2[2]+red2[3];
        float mean = t1 * (1.0f/128.0f);
        float var  = t2 * (1.0f/128.0f) - mean*mean;
        float nrm  = (o - mean)*rsqrtf(var + 1e-5f)*lgs[tid] + lbs[tid];
        outsh[tid*(GPP+1) + gi] = nrm;
        __syncthreads();
    }

    // transposed coalesced-ish writes: out[b][c][m0+gi]
    for (int t=tid; t<128*GPP; t+=128){
        int c = t / GPP, gi = t % GPP;
        out[((long)b*128 + c)*Mm + m0 + gi] = outsh[c*(GPP+1)+gi];
    }
}

// ---------------- launcher -------------------------------------------------------
extern "C" void kernel_launch(void* const* d_in, const int* in_sizes, int n_in,
                              void* d_out, int out_size){
    const float* coords = (const float*)d_in[0];
    const float* feats  = (const float*)d_in[1];
    const float* W_in   = (const float*)d_in[2];
    const float* b_in   = (const float*)d_in[3];
    const float* W_lat  = (const float*)d_in[24];
    const float* b_lat  = (const float*)d_in[25];
    const float* p_kW1  = (const float*)d_in[26];
    const float* p_kb1  = (const float*)d_in[27];
    const float* p_kW2  = (const float*)d_in[28];
    const float* p_kb2  = (const float*)d_in[29];
    const float* p_lng  = (const float*)d_in[30];
    const float* p_lnb  = (const float*)d_in[31];

    const int PROJ_SMEM = (18304 + 128*(GPP+1) + 48) * 4;

    cudaFuncSetAttribute(k_knn_self, cudaFuncAttributeMaxDynamicSharedMemorySize, Nn*16);
    cudaFuncSetAttribute(k_knn_grid, cudaFuncAttributeMaxDynamicSharedMemorySize, Nn*16);
    cudaFuncSetAttribute(k_proj,     cudaFuncAttributeMaxDynamicSharedMemorySize, PROJ_SMEM);

    float* xg; cudaGetSymbolAddress((void**)&xg, g_x);
    float* vg; cudaGetSymbolAddress((void**)&vg, g_v);
    float* pfg; cudaGetSymbolAddress((void**)&pfg, g_pf);

    k_input<<<(BN*GNNc)/256, 256>>>(feats, W_in, b_in);
    k_knn_self<<<BN/256, 256, Nn*16>>>(coords);
    k_knn_grid<<<BM/256, 256, Nn*16>>>(coords);

    for (int layer = 0; layer < 2; layer++){
        int base = 4 + layer*10;
        const float* kW1  = (const float*)d_in[base+0];
        const float* kb1  = (const float*)d_in[base+1];
        const float* kW2  = (const float*)d_in[base+2];
        const float* kb2  = (const float*)d_in[base+3];
        const float* vW   = (const float*)d_in[base+4];
        const float* vb   = (const float*)d_in[base+5];
        const float* lng  = (const float*)d_in[base+6];
        const float* lnb  = (const float*)d_in[base+7];
        const float* seW1 = (const float*)d_in[base+8];
        const float* seW2 = (const float*)d_in[base+9];

        k_rowgemm<64,64><<<256, 64>>>(xg, vW, vb, vg);
        k_zero64<<<1, 64>>>();
        k_gno_out<<<BN, 64>>>(coords, kW1, kb1, kW2, kb2);
        k_se<<<1, 64>>>(seW1, seW2);
        k_gno_ln<<<512, 64>>>(lng, lnb);
    }

    k_rowgemm<64,128><<<256, 128>>>(xg, W_lat, b_lat, pfg);
    k_proj<<<BM/GPP, 128, PROJ_SMEM>>>(coords, p_kW1, p_kb1, p_kW2, p_kb2,
                                       p_lng, p_lnb, (float*)d_out);
}

// round 3
// speedup vs baseline: 1.7310x; 1.7310x over previous
#include <cuda_runtime.h>
#include <math.h>

#define Bb   2
#define Nn   4096
#define GNNc 64
#define LATc 128
#define KG   12
#define KP   8
#define Mm   32768
#define BN   (Bb*Nn)   // 8192
#define BM   (Bb*Mm)   // 65536
#define GPP  16        // grid points per block in k_proj
#define GSTEP 4        // grid points per step in k_proj

// ---------------- scratch (static device globals; no allocation) -------------
__device__ float g_x  [BN*GNNc];
__device__ float g_v  [BN*GNNc];
__device__ float g_o  [BN*GNNc];
__device__ float g_pf [BN*LATc];
__device__ int   g_nbr[BN*KG];
__device__ int   g_gidx[BM*KP];
__device__ float g_gd2 [BM*KP];
__device__ float g_chsumP[GNNc*256];   // padded: one channel per 1KB (LTS spread)
__device__ float g_s[GNNc];

__device__ __forceinline__ float gelu_f(float x){
    return 0.5f * x * (1.0f + erff(x * 0.7071067811865476f));
}

// ---- packed f32x2 helpers (sm_103a FFMA2) ------------------------------------
__device__ __forceinline__ unsigned long long pk2(float a, float b){
    unsigned long long r;
    asm("mov.b64 %0, {%1, %2};" : "=l"(r) : "r"(__float_as_uint(a)), "r"(__float_as_uint(b)));
    return r;
}
__device__ __forceinline__ unsigned long long ffma2(unsigned long long a,
                                                    unsigned long long b,
                                                    unsigned long long c){
    unsigned long long d;
    asm("fma.rn.f32x2 %0, %1, %2, %3;" : "=l"(d) : "l"(a), "l"(b), "l"(c));
    return d;
}
__device__ __forceinline__ float2 upk2(unsigned long long a){
    unsigned int lo, hi;
    asm("mov.b64 {%0, %1}, %2;" : "=r"(lo), "=r"(hi) : "l"(a));
    float2 f; f.x = __uint_as_float(lo); f.y = __uint_as_float(hi);
    return f;
}

// ---- exact-rounding helpers matching XLA's op-by-op f32 semantics ------------
__device__ __forceinline__ float sqsum_A(float x, float y, float z){
    return __fadd_rn(__fadd_rn(__fmul_rn(x,x), __fmul_rn(y,y)), __fmul_rn(z,z));
}
__device__ __forceinline__ float dot3_gemm(float a0,float a1,float a2,
                                           float b0,float b1,float b2){
    return __fmaf_rn(a2,b2, __fmaf_rn(a1,b1, __fmul_rn(a0,b0)));
}
__device__ __forceinline__ float d2_ref(float asum, float bsum, float dot){
    return __fadd_rn(__fadd_rn(asum,bsum), __fmul_rn(-2.0f, dot));
}
__device__ __forceinline__ float grid_coord(int i){
    return (float)(-1.0 + (2.0/31.0) * (double)i);
}

template<int KK>
__device__ __forceinline__ void knn_insert(float (&kd)[KK], int (&ki)[KK], float d2, int j){
    if (d2 < kd[KK-1]){
        kd[KK-1] = d2; ki[KK-1] = j;
        #pragma unroll
        for (int r=KK-1; r>0; r--){
            if (kd[r] < kd[r-1]){
                float td=kd[r]; kd[r]=kd[r-1]; kd[r-1]=td;
                int   ti=ki[r]; ki[r]=ki[r-1]; ki[r-1]=ti;
            }
        }
    }
}

// ---------------- x = feats @ W_in + b_in ------------------------------------
__global__ void k_input(const float* __restrict__ feats,
                        const float* __restrict__ W,
                        const float* __restrict__ bias){
    int t = blockIdx.x*blockDim.x + threadIdx.x;
    if (t >= BN*GNNc) return;
    int row = t >> 6, c = t & 63;
    const float* f = feats + row*9;
    float acc = bias[c];
    #pragma unroll
    for (int j=0;j<9;j++) acc = fmaf(f[j], W[j*GNNc + c], acc);
    g_x[t] = acc;
}

// ---------------- self kNN: top-12 excluding self -----------------------------
__global__ void k_knn_self(const float* __restrict__ coords){
    extern __shared__ float4 sc[];
    int q = blockIdx.x*blockDim.x + threadIdx.x;
    int b  = q / Nn;
    int il = q % Nn;
    const float* cb = coords + b*Nn*3;
    for (int j = threadIdx.x; j < Nn; j += blockDim.x){
        float x = cb[j*3], y = cb[j*3+1], z = cb[j*3+2];
        sc[j] = make_float4(x,y,z, sqsum_A(x,y,z));
    }
    __syncthreads();
    float4 qf = sc[il];
    float kd[KG]; int ki[KG];
    #pragma unroll
    for (int r=0;r<KG;r++){ kd[r]=3.4e38f; ki[r]=0; }
    for (int j=0;j<Nn;j+=4){
        float4 f0=sc[j], f1=sc[j+1], f2=sc[j+2], f3=sc[j+3];
        float d0 = d2_ref(qf.w, f0.w, dot3_gemm(qf.x,qf.y,qf.z, f0.x,f0.y,f0.z));
        float d1 = d2_ref(qf.w, f1.w, dot3_gemm(qf.x,qf.y,qf.z, f1.x,f1.y,f1.z));
        float d2 = d2_ref(qf.w, f2.w, dot3_gemm(qf.x,qf.y,qf.z, f2.x,f2.y,f2.z));
        float d3 = d2_ref(qf.w, f3.w, dot3_gemm(qf.x,qf.y,qf.z, f3.x,f3.y,f3.z));
        if (j   == il) d0 = 3.5e38f;
        if (j+1 == il) d1 = 3.5e38f;
        if (j+2 == il) d2 = 3.5e38f;
        if (j+3 == il) d3 = 3.5e38f;
        knn_insert(kd,ki,d0,j);
        knn_insert(kd,ki,d1,j+1);
        knn_insert(kd,ki,d2,j+2);
        knn_insert(kd,ki,d3,j+3);
    }
    #pragma unroll
    for (int r=0;r<KG;r++) g_nbr[q*KG + r] = ki[r];
}

// ---------------- grid kNN: top-8 (stores d2 too) -----------------------------
__global__ void k_knn_grid(const float* __restrict__ coords){
    extern __shared__ float4 sc[];
    int q = blockIdx.x*blockDim.x + threadIdx.x;
    int b = q / Mm;
    int m = q % Mm;
    const float* cb = coords + b*Nn*3;
    for (int j = threadIdx.x; j < Nn; j += blockDim.x){
        float x = cb[j*3], y = cb[j*3+1], z = cb[j*3+2];
        sc[j] = make_float4(x,y,z, sqsum_A(x,y,z));
    }
    __syncthreads();
    float px = grid_coord( m        & 31);
    float py = grid_coord((m >> 5)  & 31);
    float pz = grid_coord( m >> 10      );
    float pp = sqsum_A(px,py,pz);
    float kd[KP]; int ki[KP];
    #pragma unroll
    for (int r=0;r<KP;r++){ kd[r]=3.4e38f; ki[r]=0; }
    for (int j=0;j<Nn;j+=4){
        float4 f0=sc[j], f1=sc[j+1], f2=sc[j+2], f3=sc[j+3];
        float d0 = d2_ref(pp, f0.w, dot3_gemm(px,py,pz, f0.x,f0.y,f0.z));
        float d1 = d2_ref(pp, f1.w, dot3_gemm(px,py,pz, f1.x,f1.y,f1.z));
        float d2 = d2_ref(pp, f2.w, dot3_gemm(px,py,pz, f2.x,f2.y,f2.z));
        float d3 = d2_ref(pp, f3.w, dot3_gemm(px,py,pz, f3.x,f3.y,f3.z));
        knn_insert(kd,ki,d0,j);
        knn_insert(kd,ki,d1,j+1);
        knn_insert(kd,ki,d2,j+2);
        knn_insert(kd,ki,d3,j+3);
    }
    #pragma unroll
    for (int r=0;r<KP;r++){
        g_gidx[q*KP + r] = ki[r];
        g_gd2 [q*KP + r] = kd[r];
    }
}

// ---------------- row GEMM Y = X@W + b (IN=64), warp-per-row -------------------
template<int OUT>
__global__ void k_rowgemm(const float* __restrict__ X,
                          const float* __restrict__ W,
                          const float* __restrict__ bias,
                          float* __restrict__ Y){
    __shared__ float Ws[64*OUT];
    __shared__ float xs[8][64];
    int tid = threadIdx.x;
    for (int t=tid; t<64*OUT; t+=256) Ws[t]=W[t];
    int w = tid>>5, l = tid&31;
    int r0 = blockIdx.x*8;
    for (int t=tid; t<512; t+=256) xs[t>>6][t&63] = X[(r0 + (t>>6))*64 + (t&63)];
    __syncthreads();
    int r = r0 + w;
    float acc[OUT/32];
    #pragma unroll
    for (int i=0;i<OUT/32;i++) acc[i] = bias[l + i*32];
    #pragma unroll 8
    for (int j=0;j<64;j++){
        float xj = xs[w][j];
        #pragma unroll
        for (int i=0;i<OUT/32;i++) acc[i] = fmaf(xj, Ws[j*OUT + l + i*32], acc[i]);
    }
    #pragma unroll
    for (int i=0;i<OUT/32;i++) Y[r*OUT + l + i*32] = acc[i];
}

// ---------------- zero channel sums -------------------------------------------
__global__ void k_zero64(){ g_chsumP[threadIdx.x*256] = 0.0f; }

// ---------------- GNO message passing: 4 points per 256-thread block ----------
__global__ void k_gno_out(const float* __restrict__ coords,
                          const float* __restrict__ kW1, const float* __restrict__ kb1,
                          const float* __restrict__ kW2, const float* __restrict__ kb2){
    __shared__ float W1s[96], b1s[32], W2s[32*64], b2s[64];
    __shared__ float gsh[4][KG*32];
    __shared__ float relb[4][KG][3];
    __shared__ int   ji[4][KG];
    __shared__ float psum[256];
    int tid = threadIdx.x;
    int p = tid>>6, c = tid&63;
    int pt0 = blockIdx.x*4;
    for (int t=tid; t<2048; t+=256) W2s[t]=kW2[t];
    if (tid < 96) W1s[tid]=kW1[tid];
    else if (tid < 128) b1s[tid-96]=kb1[tid-96];
    else if (tid < 192) b2s[tid-128]=kb2[tid-128];
    if (tid < 4*KG){
        int pl = tid/KG, k = tid%KG;
        int gp = pt0 + pl;
        int b = gp/Nn, i = gp%Nn;
        const float* cb = coords + b*Nn*3;
        int j = g_nbr[gp*KG + k];
        ji[pl][k] = j;
        relb[pl][k][0] = cb[j*3]  -cb[i*3];
        relb[pl][k][1] = cb[j*3+1]-cb[i*3+1];
        relb[pl][k][2] = cb[j*3+2]-cb[i*3+2];
    }
    __syncthreads();
    for (int t=tid; t<4*KG*32; t+=256){
        int pl = t/384; int rem = t - pl*384;
        int k = rem>>5, h = rem&31;
        float d = fmaf(relb[pl][k][2], W1s[64+h],
                  fmaf(relb[pl][k][1], W1s[32+h],
                  fmaf(relb[pl][k][0], W1s[h], b1s[h])));
        gsh[pl][rem] = gelu_f(d);
    }
    __syncthreads();
    int gp = pt0 + p;
    int b = gp/Nn;
    float outc = 0.0f, b2c = b2s[c];
    #pragma unroll
    for (int k=0;k<KG;k++){
        float vn = g_v[(b*Nn + ji[p][k])*GNNc + c];
        float s = b2c;
        #pragma unroll
        for (int h=0;h<32;h++) s = fmaf(gsh[p][k*32+h], W2s[h*64+c], s);
        outc = fmaf(s, vn, outc);
    }
    g_o[gp*GNNc + c] = outc;
    psum[tid] = outc;
    __syncthreads();
    if (tid < 64){
        float s = psum[tid]+psum[tid+64]+psum[tid+128]+psum[tid+192];
        atomicAdd(&g_chsumP[tid*256], s);
    }
}

// ---------------- squeeze-excite gate ------------------------------------------
__global__ void k_se(const float* __restrict__ seW1, const float* __restrict__ seW2){
    __shared__ float ms[64], hs[16];
    int c = threadIdx.x;
    ms[c] = g_chsumP[c*256] * (1.0f/(float)BN);
    __syncthreads();
    if (c < 16){
        float a=0.f;
        #pragma unroll
        for (int j=0;j<64;j++) a = fmaf(ms[j], seW1[j*16+c], a);
        hs[c] = gelu_f(a);
    }
    __syncthreads();
    float a=0.f;
    #pragma unroll
    for (int h=0;h<16;h++) a = fmaf(hs[h], seW2[h*64+c], a);
    g_s[c] = 1.0f/(1.0f + expf(-a));
}

// ---------------- x = LN(gelu(out*s + v)), warp-per-row -------------------------
__global__ void k_gno_ln(const float* __restrict__ lng, const float* __restrict__ lnb){
    int tid = threadIdx.x;
    int w = tid>>5, l = tid&31;
    int r = blockIdx.x*8 + w;
    float s0 = g_s[l], s1 = g_s[l+32];
    float y0 = gelu_f(fmaf(g_o[r*64+l],    s0, g_v[r*64+l]));
    float y1 = gelu_f(fmaf(g_o[r*64+l+32], s1, g_v[r*64+l+32]));
    float t1 = y0+y1, t2 = y0*y0 + y1*y1;
    #pragma unroll
    for (int off=16; off>0; off>>=1){
        t1 += __shfl_xor_sync(0xffffffffu, t1, off);
        t2 += __shfl_xor_sync(0xffffffffu, t2, off);
    }
    float mean = t1*(1.0f/64.0f);
    float var  = t2*(1.0f/64.0f) - mean*mean;
    float rs   = rsqrtf(var + 1e-5f);
    g_x[r*64+l]    = (y0-mean)*rs*lng[l]    + lnb[l];
    g_x[r*64+l+32] = (y1-mean)*rs*lng[l+32] + lnb[l+32];
}

// ---------------- fused projection + LN (dominant kernel, FFMA2) ----------------
// smem layout (floats):
//  [0,16384)      W2q  : channel-quad packed W2: float4(W2[j][c],c+32,c+64,c+96) at [j*32+c]
//  [16384,20480)  ht   : h values, [gih][j][k] flat (4*128*8)
//  [20480,22656)  outsh: [c][gi] stride 17 (128*17)
//  [22656,23040)  W1s  (384)
//  [23040,23168)  b1s
//  [23168,23296)  b2s
//  [23296,23424)  lgs
//  [23424,23552)  lbs
//  [23552,23648)  relb (4*8*3)
//  [23648,23680)  wr   (4*8)
//  [23680,23712)  ji   (4*8 int)
#define PROJ_SMEM_FLOATS 23712
__global__ void __launch_bounds__(128) k_proj(const float* __restrict__ coords,
        const float* __restrict__ W1, const float* __restrict__ b1,
        const float* __restrict__ W2, const float* __restrict__ b2,
        const float* __restrict__ lng, const float* __restrict__ lnb,
        float* __restrict__ out){
    extern __shared__ float sh[];
    float*  W2q   = sh;
    float*  ht    = sh + 16384;
    float*  outsh = sh + 20480;
    float*  W1s   = sh + 22656;
    float*  b1s   = sh + 23040;
    float*  b2s   = sh + 23168;
    float*  lgs   = sh + 23296;
    float*  lbs   = sh + 23424;
    float*  relb  = sh + 23552;   // [gih*24 + k*3 + d]
    float*  wr    = sh + 23648;   // [gih*8 + k]
    int*    ji    = (int*)(sh + 23680);

    int tid = threadIdx.x;
    // pack W2 into channel quads
    for (int t=tid; t<4096; t+=128){
        int j = t>>5, c = t&31;
        ((float4*)W2q)[t] = make_float4(W2[j*128+c], W2[j*128+c+32],
                                        W2[j*128+c+64], W2[j*128+c+96]);
    }
    for (int t=tid; t<384; t+=128) W1s[t]=W1[t];
    b1s[tid]=b1[tid]; b2s[tid]=b2[tid]; lgs[tid]=lng[tid]; lbs[tid]=lnb[tid];

    int base = blockIdx.x * GPP;
    int b  = base / Mm;
    int m0 = base % Mm;
    const float* cb = coords + b*Nn*3;
    __syncthreads();

    int gihp = tid>>5, cp = tid&31;   // phase-2 identity: warp = grid point

    for (int s=0; s<GPP/GSTEP; s++){
        int gi0 = s*GSTEP;
        // setup: 32 threads = 4 gi x 8 k
        if (tid < GSTEP*KP){
            int gih = tid>>3, k = tid&7;
            int m = m0 + gi0 + gih;
            float px = grid_coord( m        & 31);
            float py = grid_coord((m >> 5)  & 31);
            float pz = grid_coord( m >> 10      );
            long qk = (long)(b*Mm + m)*KP + k;
            int id  = g_gidx[qk];
            float d2 = g_gd2[qk];
            float dist = sqrtf(fmaxf(d2, 1e-12f));
            wr[gih*8+k] = 1.0f/(dist + 1e-6f);
            ji[gih*8+k] = id;
            relb[gih*24 + k*3+0] = px - cb[id*3];
            relb[gih*24 + k*3+1] = py - cb[id*3+1];
            relb[gih*24 + k*3+2] = pz - cb[id*3+2];
        }
        __syncthreads();

        // prefetch pf rows for this thread's grid point (4 channels x 8 nbrs)
        float pfq[KP][4];
        #pragma unroll
        for (int k=0;k<KP;k++){
            const float* pfr = g_pf + (long)(b*Nn + ji[gihp*8+k])*LATc + cp;
            pfq[k][0]=pfr[0]; pfq[k][1]=pfr[32]; pfq[k][2]=pfr[64]; pfq[k][3]=pfr[96];
        }

        // phase 1: thread = hidden unit j (=tid), all 4 gi
        {
            float w0=W1s[tid], w1=W1s[128+tid], w2w=W1s[256+tid], bb=b1s[tid];
            #pragma unroll
            for (int gih=0; gih<GSTEP; gih++){
                float hv[KP];
                #pragma unroll
                for (int k=0;k<KP;k++){
                    float d = fmaf(relb[gih*24+k*3+2], w2w,
                              fmaf(relb[gih*24+k*3+1], w1,
                              fmaf(relb[gih*24+k*3+0], w0, bb)));
                    hv[k] = gelu_f(d);
                }
                float* hp = ht + gih*1024 + tid*8;
                ((float4*)hp)[0] = make_float4(hv[0],hv[1],hv[2],hv[3]);
                ((float4*)hp)[1] = make_float4(hv[4],hv[5],hv[6],hv[7]);
            }
        }
        __syncthreads();

        // phase 2: warp gihp handles grid point gi0+gihp; lane cp -> 4 channels
        unsigned long long acc[16];
        #pragma unroll
        for (int i=0;i<16;i++) acc[i]=0ull;
        const float4* w4 = (const float4*)W2q;
        const ulonglong2* hp = (const ulonglong2*)(ht + gihp*1024);
        #pragma unroll 2
        for (int j=0;j<128;j++){
            float4 wq = w4[j*32 + cp];
            unsigned long long ww0 = pk2(wq.x, wq.x);
            unsigned long long ww1 = pk2(wq.y, wq.y);
            unsigned long long ww2 = pk2(wq.z, wq.z);
            unsigned long long ww3 = pk2(wq.w, wq.w);
            ulonglong2 hA = hp[j*2];
            ulonglong2 hB = hp[j*2+1];
            acc[0]  = ffma2(hA.x, ww0, acc[0]);
            acc[1]  = ffma2(hA.y, ww0, acc[1]);
            acc[2]  = ffma2(hB.x, ww0, acc[2]);
            acc[3]  = ffma2(hB.y, ww0, acc[3]);
            acc[4]  = ffma2(hA.x, ww1, acc[4]);
            acc[5]  = ffma2(hA.y, ww1, acc[5]);
            acc[6]  = ffma2(hB.x, ww1, acc[6]);
            acc[7]  = ffma2(hB.y, ww1, acc[7]);
            acc[8]  = ffma2(hA.x, ww2, acc[8]);
            acc[9]  = ffma2(hA.y, ww2, acc[9]);
            acc[10] = ffma2(hB.x, ww2, acc[10]);
            acc[11] = ffma2(hB.y, ww2, acc[11]);
            acc[12] = ffma2(hA.x, ww3, acc[12]);
            acc[13] = ffma2(hA.y, ww3, acc[13]);
            acc[14] = ffma2(hB.x, ww3, acc[14]);
            acc[15] = ffma2(hB.y, ww3, acc[15]);
        }

        float wrk[KP];
        #pragma unroll
        for (int k=0;k<KP;k++) wrk[k] = wr[gihp*8+k];
        float wsum = 0.f;
        #pragma unroll
        for (int k=0;k<KP;k++) wsum += wrk[k];
        float inv_wsum = 1.0f/wsum;

        float oq[4];
        #pragma unroll
        for (int q=0;q<4;q++){
            float b2c = b2s[cp + q*32];
            float2 p0 = upk2(acc[q*4+0]);
            float2 p1 = upk2(acc[q*4+1]);
            float2 p2 = upk2(acc[q*4+2]);
            float2 p3 = upk2(acc[q*4+3]);
            float o = 0.f;
            o = fmaf((p0.x+b2c)*wrk[0], pfq[0][q], o);
            o = fmaf((p0.y+b2c)*wrk[1], pfq[1][q], o);
            o = fmaf((p1.x+b2c)*wrk[2], pfq[2][q], o);
            o = fmaf((p1.y+b2c)*wrk[3], pfq[3][q], o);
            o = fmaf((p2.x+b2c)*wrk[4], pfq[4][q], o);
            o = fmaf((p2.y+b2c)*wrk[5], pfq[5][q], o);
            o = fmaf((p3.x+b2c)*wrk[6], pfq[6][q], o);
            o = fmaf((p3.y+b2c)*wrk[7], pfq[7][q], o);
            oq[q] = o * inv_wsum;
        }

        // LayerNorm over 128 channels: fully warp-local (warp = grid point)
        float s1 = oq[0]+oq[1]+oq[2]+oq[3];
        float s2 = oq[0]*oq[0]+oq[1]*oq[1]+oq[2]*oq[2]+oq[3]*oq[3];
        #pragma unroll
        for (int off=16; off>0; off>>=1){
            s1 += __shfl_xor_sync(0xffffffffu, s1, off);
            s2 += __shfl_xor_sync(0xffffffffu, s2, off);
        }
        float mean = s1*(1.0f/128.0f);
        float var  = s2*(1.0f/128.0f) - mean*mean;
        float rs   = rsqrtf(var + 1e-5f);
        int gi = gi0 + gihp;
        #pragma unroll
        for (int q=0;q<4;q++){
            int c = cp + q*32;
            outsh[c*17 + gi] = (oq[q]-mean)*rs*lgs[c] + lbs[c];
        }
        __syncthreads();
    }

    for (int t=tid; t<128*GPP; t+=128){
        int c = t >> 4, gi = t & 15;
        out[((long)b*128 + c)*Mm + m0 + gi] = outsh[c*17+gi];
    }
}

// ---------------- launcher -------------------------------------------------------
extern "C" void kernel_launch(void* const* d_in, const int* in_sizes, int n_in,
                              void* d_out, int out_size){
    const float* coords = (const float*)d_in[0];
    const float* feats  = (const float*)d_in[1];
    const float* W_in   = (const float*)d_in[2];
    const float* b_in   = (const float*)d_in[3];
    const float* W_lat  = (const float*)d_in[24];
    const float* b_lat  = (const float*)d_in[25];
    const float* p_kW1  = (const float*)d_in[26];
    const float* p_kb1  = (const float*)d_in[27];
    const float* p_kW2  = (const float*)d_in[28];
    const float* p_kb2  = (const float*)d_in[29];
    const float* p_lng  = (const float*)d_in[30];
    const float* p_lnb  = (const float*)d_in[31];

    const int PROJ_SMEM = PROJ_SMEM_FLOATS * 4;

    cudaFuncSetAttribute(k_knn_self, cudaFuncAttributeMaxDynamicSharedMemorySize, Nn*16);
    cudaFuncSetAttribute(k_knn_grid, cudaFuncAttributeMaxDynamicSharedMemorySize, Nn*16);
    cudaFuncSetAttribute(k_proj,     cudaFuncAttributeMaxDynamicSharedMemorySize, PROJ_SMEM);

    float* xg; cudaGetSymbolAddress((void**)&xg, g_x);
    float* vg; cudaGetSymbolAddress((void**)&vg, g_v);
    float* pfg; cudaGetSymbolAddress((void**)&pfg, g_pf);

    k_input<<<(BN*GNNc)/256, 256>>>(feats, W_in, b_in);
    k_knn_self<<<BN/256, 256, Nn*16>>>(coords);
    k_knn_grid<<<BM/256, 256, Nn*16>>>(coords);

    for (int layer = 0; layer < 2; layer++){
        int base = 4 + layer*10;
        const float* kW1  = (const float*)d_in[base+0];
        const float* kb1  = (const float*)d_in[base+1];
        const float* kW2  = (const float*)d_in[base+2];
        const float* kb2  = (const float*)d_in[base+3];
        const float* vW   = (const float*)d_in[base+4];
        const float* vb   = (const float*)d_in[base+5];
        const float* lng  = (const float*)d_in[base+6];
        const float* lnb  = (const float*)d_in[base+7];
        const float* seW1 = (const float*)d_in[base+8];
        const float* seW2 = (const float*)d_in[base+9];

        k_rowgemm<64><<<BN/8, 256>>>(xg, vW, vb, vg);
        k_zero64<<<1, 64>>>();
        k_gno_out<<<BN/4, 256>>>(coords, kW1, kb1, kW2, kb2);
        k_se<<<1, 64>>>(seW1, seW2);
        k_gno_ln<<<BN/8, 256>>>(lng, lnb);
    }

    k_rowgemm<128><<<BN/8, 256>>>(xg, W_lat, b_lat, pfg);
    k_proj<<<BM/GPP, 128, PROJ_SMEM>>>(coords, p_kW1, p_kb1, p_kW2, p_kb2,
                                       p_lng, p_lnb, (float*)d_out);
}